// round 5
// baseline (speedup 1.0000x reference)
#include <cuda_runtime.h>

#define EPSV 1e-5f

// ---- scratch (__device__ globals) ----
__device__ float g_z[16*320*256];      // pooled x
__device__ float g_ps[5120];           // per-plane sum
__device__ float g_ps2[5120];          // per-plane sumsq
__device__ float g_z1p[16*16*8*256];   // conv1 partials (16 chunks)
__device__ float g_z1[16*8*256];       // conv1 out (residual base)
__device__ float g_cm[128];            // per (b,c) GN mean
__device__ float g_cr[128];            // per (b,c) GN rstd
__device__ float g_att[16*8*256];
__device__ float g_apad[16*8*18*18];   // silu(gn2) 16x16, zero-padded border

__device__ __forceinline__ float siluf(float x){
    return __fdividef(x, 1.0f+__expf(-x));
}

__device__ __forceinline__ float redsum256(float v, float* sb){
    #pragma unroll
    for(int o=16;o;o>>=1) v += __shfl_xor_sync(0xffffffffu, v, o);
    if((threadIdx.x&31)==0) sb[threadIdx.x>>5]=v;
    __syncthreads();
    float r = sb[0]+sb[1]+sb[2]+sb[3]+sb[4]+sb[5]+sb[6]+sb[7];
    __syncthreads();
    return r;
}

// ---- K1: 4x4 average pool + exact per-plane stats ----
__global__ void k_pool(const float* __restrict__ x){
    __shared__ float sb[8];
    int plane = blockIdx.x;            // b*320 + c
    int t = threadIdx.x;
    int Y = t>>4, X = t&15;
    const float4* xr = (const float4*)(x + (size_t)plane*4096);
    float s = 0.f;
    #pragma unroll
    for(int r=0;r<4;r++){
        float4 v = xr[(4*Y+r)*16 + X];
        s += v.x+v.y+v.z+v.w;
    }
    float v = s*(1.0f/16.0f);
    g_z[plane*256 + t] = v;
    float P = redsum256(v, sb);
    float Q = redsum256(v*v, sb);
    if(t==0){ g_ps[plane]=P; g_ps2[plane]=Q; }
}

// ---- K2: conv1 (320->8, 3x3 SAME, 16x16), GN1(32)+SiLU fused; 20-ch chunks ----
__global__ void __launch_bounds__(256) k_conv1(const float* __restrict__ g1,
                                               const float* __restrict__ b1,
                                               const float* __restrict__ w1){
    __shared__ float sp[20*324];
    __shared__ __align__(16) float sw[20*72];    // [ci][k][o]
    __shared__ float sm2[2], sr2[2];
    int j = blockIdx.x, b = blockIdx.y;
    int t = threadIdx.x;
    if(t<2){
        float s=0.f,s2=0.f;
        #pragma unroll
        for(int i=0;i<10;i++){
            int pl = b*320 + (j*2+t)*10 + i;
            s += g_ps[pl]; s2 += g_ps2[pl];
        }
        float m = s*(1.0f/2560.0f);
        sm2[t]=m; sr2[t]=rsqrtf(s2*(1.0f/2560.0f)-m*m+EPSV);
    }
    for(int i=t;i<1440;i+=256){
        int ci = i/72, r = i-ci*72, k = r>>3, o = r&7;
        sw[i] = w1[o*2880 + (j*20+ci)*9 + k];
    }
    __syncthreads();
    for(int i=t;i<6480;i+=256){
        int ci = i/324, p = i-ci*324;
        int r18 = p/18, c18 = p-r18*18;
        float val = 0.f;
        if(r18>=1 && r18<=16 && c18>=1 && c18<=16){
            int c = j*20+ci;
            float v = g_z[((b*320+c)<<8) + (r18-1)*16 + (c18-1)];
            val = siluf((v-sm2[ci/10])*sr2[ci/10]*g1[c] + b1[c]);
        }
        sp[i]=val;
    }
    __syncthreads();
    int Y = t>>4, X = t&15;
    float acc[8];
    #pragma unroll
    for(int o=0;o<8;o++) acc[o]=0.f;
    #pragma unroll
    for(int ci=0;ci<20;ci++){
        float a[9];
        #pragma unroll
        for(int dy=0;dy<3;dy++)
            #pragma unroll
            for(int dx=0;dx<3;dx++)
                a[dy*3+dx] = sp[ci*324 + (Y+dy)*18 + (X+dx)];
        #pragma unroll
        for(int k=0;k<9;k++){
            float av = a[k];
            float4 wA = *(const float4*)&sw[((ci*9+k)<<3)];
            float4 wB = *(const float4*)&sw[((ci*9+k)<<3)+4];
            acc[0]+=av*wA.x; acc[1]+=av*wA.y; acc[2]+=av*wA.z; acc[3]+=av*wA.w;
            acc[4]+=av*wB.x; acc[5]+=av*wB.y; acc[6]+=av*wB.z; acc[7]+=av*wB.w;
        }
    }
    #pragma unroll
    for(int o=0;o<8;o++)
        g_z1p[(((j*16+b)*8+o)<<8) + t] = acc[o];
}

// ---- K3: merge partials + bias; per-channel GN stats ----
__global__ void k_merge(const float* __restrict__ bc1){
    __shared__ float sb[8];
    int bc = blockIdx.x;               // b*8 + c
    int b = bc>>3, c = bc&7;
    int t = threadIdx.x;
    float s = bc1[c];
    #pragma unroll
    for(int jj=0;jj<16;jj++)
        s += g_z1p[(((jj*16+b)*8+c)<<8) + t];
    g_z1[bc*256 + t] = s;
    float P = redsum256(s, sb);
    float Q = redsum256(s*s, sb);
    if(t==0){
        float m = P*(1.f/256.f);
        g_cm[bc]=m;
        g_cr[bc]=rsqrtf(Q*(1.f/256.f)-m*m+EPSV);
    }
}

// ---- K4: GN-apply + qkv + attention (no max pass: |logits| << 1), 4 thr/row ----
__global__ void __launch_bounds__(1024) k_attn(const float* __restrict__ ga,
                                               const float* __restrict__ ba,
                                               const float* __restrict__ wq,
                                               const float* __restrict__ bq){
    __shared__ float2 sq[256], sk[256], sv[256];
    __shared__ float swq[192];
    int b = blockIdx.x>>2, h = blockIdx.x&3;
    int t = threadIdx.x;
    if(t<192) swq[t] = wq[t];
    __syncthreads();
    if(t<256){
        float nv[8];
        #pragma unroll
        for(int c=0;c<8;c++){
            int bc = b*8+c;
            float z = g_z1[bc*256+t];
            nv[c] = (z-g_cm[bc])*g_cr[bc]*ga[c] + ba[c];
        }
        float q0=bq[2*h], q1=bq[2*h+1];
        float k0=bq[8+2*h], k1=bq[9+2*h];
        float v0=bq[16+2*h], v1=bq[17+2*h];
        #pragma unroll
        for(int c=0;c<8;c++){
            q0 += swq[(2*h  )*8+c]*nv[c];
            q1 += swq[(2*h+1)*8+c]*nv[c];
            k0 += swq[(8+2*h)*8+c]*nv[c];
            k1 += swq[(9+2*h)*8+c]*nv[c];
            v0 += swq[(16+2*h)*8+c]*nv[c];
            v1 += swq[(17+2*h)*8+c]*nv[c];
        }
        const float scale = 0.7071067811865475f;
        sq[t] = make_float2(q0*scale, q1*scale);
        sk[t] = make_float2(k0,k1);
        sv[t] = make_float2(v0,v1);
    }
    __syncthreads();
    int row = t>>2, ch = t&3;
    float2 qq = sq[row];
    float den=0.f, a0=0.f, a1=0.f;
    int m0 = ch*64;
    #pragma unroll 8
    for(int m=m0;m<m0+64;m++){
        float2 kk = sk[m];
        float e = __expf(qq.x*kk.x + qq.y*kk.y);
        float2 vv = sv[m];
        den += e;
        a0 += e*vv.x; a1 += e*vv.y;
    }
    #pragma unroll
    for(int msk=1;msk<4;msk<<=1){
        den += __shfl_xor_sync(0xffffffffu, den, msk);
        a0  += __shfl_xor_sync(0xffffffffu, a0,  msk);
        a1  += __shfl_xor_sync(0xffffffffu, a1,  msk);
    }
    if(ch==0){
        float inv = __fdividef(1.0f, den);
        g_att[(b*8 + 2*h  )*256 + row] = a0*inv;
        g_att[(b*8 + 2*h+1)*256 + row] = a1*inv;
    }
}

// ---- K5: proj+res + LN + MLP(gelu) + res + GN2 + SiLU -> padded; 4 thr/pixel ----
__global__ void __launch_bounds__(1024) k_mlpapad(
        const float* __restrict__ wp, const float* __restrict__ bp,
        const float* __restrict__ lng, const float* __restrict__ lnb,
        const float* __restrict__ wf1, const float* __restrict__ bf1,
        const float* __restrict__ wf2, const float* __restrict__ bf2,
        const float* __restrict__ g2, const float* __restrict__ b2){
    __shared__ float sred[16*32];
    __shared__ float sredt[16];
    int b = blockIdx.x, t = threadIdx.x;
    int p = t>>2, q4 = t&3;
    float ao[8], z2[8];
    #pragma unroll
    for(int c=0;c<8;c++) ao[c] = g_att[(b*8+c)*256+p];
    #pragma unroll
    for(int c=0;c<8;c++){
        float s = bp[c] + g_z1[(b*8+c)*256+p];
        #pragma unroll
        for(int d=0;d<8;d++) s += wp[c*8+d]*ao[d];
        z2[c]=s;
    }
    float mu=0.f;
    #pragma unroll
    for(int c=0;c<8;c++) mu += z2[c];
    mu *= 0.125f;
    float var=0.f;
    #pragma unroll
    for(int c=0;c<8;c++){ float d=z2[c]-mu; var += d*d; }
    float rsl = rsqrtf(var*0.125f + EPSV);
    float ln[8];
    #pragma unroll
    for(int c=0;c<8;c++) ln[c] = (z2[c]-mu)*rsl*lng[c] + lnb[c];
    // each of the 4 threads handles 4 of the 16 hidden units
    float hg[4];
    #pragma unroll
    for(int u=0;u<4;u++){
        int jj = q4*4+u;
        float s = bf1[jj];
        #pragma unroll
        for(int c=0;c<8;c++) s += wf1[jj*8+c]*ln[c];
        hg[u] = 0.5f*s*(1.0f + erff(s*0.7071067811865475f));
    }
    float z3[8];
    #pragma unroll
    for(int c=0;c<8;c++){
        float s = 0.f;
        #pragma unroll
        for(int u=0;u<4;u++) s += wf2[c*16 + q4*4+u]*hg[u];
        #pragma unroll
        for(int msk=1;msk<4;msk<<=1) s += __shfl_xor_sync(0xffffffffu, s, msk);
        z3[c] = z2[c] + bf2[c] + s;
    }
    // GN2 stats (each pixel counted 4x -> divide by 1024)
    float red[16];
    #pragma unroll
    for(int c=0;c<8;c++){ red[c]=z3[c]; red[8+c]=z3[c]*z3[c]; }
    #pragma unroll
    for(int q=0;q<16;q++)
        #pragma unroll
        for(int o=16;o;o>>=1) red[q] += __shfl_xor_sync(0xffffffffu, red[q], o);
    if((t&31)==0){
        #pragma unroll
        for(int q=0;q<16;q++) sred[q*32 + (t>>5)] = red[q];
    }
    __syncthreads();
    if(t<16){
        float tot=0.f;
        #pragma unroll
        for(int w=0;w<32;w++) tot += sred[t*32+w];
        sredt[t]=tot;
    }
    __syncthreads();
    if(q4==0){
        int Y=p>>4, X=p&15;
        #pragma unroll
        for(int c=0;c<8;c++){
            float m = sredt[c]*(1.f/1024.f);
            float rs = rsqrtf(sredt[8+c]*(1.f/1024.f)-m*m+EPSV);
            float a = siluf((z3[c]-m)*rs*g2[c] + b2[c]);
            g_apad[(b*8+c)*324 + (Y+1)*18 + (X+1)] = a;
        }
    }
}

// ---- K6: fused upsample+conv2 (8->320) as stride-4 transposed conv (scalar) ----
__global__ void __launch_bounds__(256) k_conv2(const float* __restrict__ w2,
                                               const float* __restrict__ bc2,
                                               float* __restrict__ out){
    __shared__ float sa[2592];   // a_pad[b]: 8 x 18 x 18
    __shared__ float sw[1152];   // collapsed 6x6 weights for 4 o-channels
    int og = blockIdx.x, b = blockIdx.y;
    int t = threadIdx.x;
    for(int i=t;i<2592;i+=256) sa[i] = g_apad[b*2592+i];
    for(int i=t;i<1152;i+=256){
        int ol=i/288, r=i-ol*288, c=r/36, q=r-c*36, ky=q/6, kx=q-ky*6;
        int o = og*4+ol;
        int dy0 = max(0, 2-ky), dy1 = min(2, 5-ky);
        int dx0 = max(0, 2-kx), dx1 = min(2, 5-kx);
        float s=0.f;
        for(int dy=dy0;dy<=dy1;dy++)
            for(int dx=dx0;dx<=dx1;dx++)
                s += w2[o*72 + c*9 + dy*3 + dx];
        sw[i] = s;
    }
    __syncthreads();
    int ol = t>>6, u = t&63, Yq = u>>2, Xs = u&3;
    int o = og*4+ol;
    float bias = bc2[o];
    float acc[64];
    #pragma unroll
    for(int i=0;i<64;i++) acc[i]=bias;
    const int RYof[6]={3,0,1,2,3,0};
    const int RWof[6]={2,1,1,1,1,0};
    const int XL0[6] ={3,0,1,2,3,0};
    const int SCB[6] ={2,1,1,1,1,0};
    #pragma unroll
    for(int c=0;c<8;c++){
        float aw[3][6];
        #pragma unroll
        for(int r=0;r<3;r++)
            #pragma unroll
            for(int cc=0;cc<6;cc++)
                aw[r][cc] = sa[(c*18 + Yq + r)*18 + 4*Xs + cc];
        const float* wc = &sw[(ol*8 + c)*36];
        #pragma unroll
        for(int ky=0;ky<6;ky++){
            int ry = RYof[ky], riw = RWof[ky];
            #pragma unroll
            for(int kx=0;kx<6;kx++){
                float w = wc[ky*6+kx];
                int xl0 = XL0[kx], scb = SCB[kx];
                #pragma unroll
                for(int j=0;j<4;j++)
                    acc[ry*16 + xl0 + 4*j] += w * aw[riw][scb + j];
            }
        }
    }
    float4* ob = (float4*)(out + ((size_t)(b*320 + o)*64 + 4*Yq)*64 + 16*Xs);
    #pragma unroll
    for(int ry=0;ry<4;ry++)
        #pragma unroll
        for(int j=0;j<4;j++)
            ob[ry*16 + j] = make_float4(acc[ry*16+j*4], acc[ry*16+j*4+1],
                                        acc[ry*16+j*4+2], acc[ry*16+j*4+3]);
}

extern "C" void kernel_launch(void* const* d_in, const int* in_sizes, int n_in,
                              void* d_out, int out_size) {
    const float* x   = (const float*)d_in[0];
    const float* g1  = (const float*)d_in[1];
    const float* b1  = (const float*)d_in[2];
    const float* w1  = (const float*)d_in[3];
    const float* bc1 = (const float*)d_in[4];
    const float* ga  = (const float*)d_in[5];
    const float* ba  = (const float*)d_in[6];
    const float* wq  = (const float*)d_in[7];
    const float* bq  = (const float*)d_in[8];
    const float* wp  = (const float*)d_in[9];
    const float* bp  = (const float*)d_in[10];
    const float* lng = (const float*)d_in[11];
    const float* lnb = (const float*)d_in[12];
    const float* wf1 = (const float*)d_in[13];
    const float* bf1 = (const float*)d_in[14];
    const float* wf2 = (const float*)d_in[15];
    const float* bf2 = (const float*)d_in[16];
    const float* g2  = (const float*)d_in[17];
    const float* b2  = (const float*)d_in[18];
    const float* w2  = (const float*)d_in[19];
    const float* bc2 = (const float*)d_in[20];
    float* out = (float*)d_out;

    k_pool   <<<5120, 256>>>(x);
    k_conv1  <<<dim3(16,16), 256>>>(g1, b1, w1);
    k_merge  <<<128, 256>>>(bc1);
    k_attn   <<<64, 1024>>>(ga, ba, wq, bq);
    k_mlpapad<<<16, 1024>>>(wp, bp, lng, lnb, wf1, bf1, wf2, bf2, g2, b2);
    k_conv2  <<<dim3(80,16), 256>>>(w2, bc2, out);
}

// round 6
// speedup vs baseline: 1.1828x; 1.1828x over previous
#include <cuda_runtime.h>

#define EPSV 1e-5f

// ---- scratch (__device__ globals) ----
__device__ float g_z[16*320*256];      // pooled x
__device__ float g_ps[5120];           // per-plane sum
__device__ float g_ps2[5120];          // per-plane sumsq
__device__ float g_z1p[32*16*8*256];   // conv1 partials (32 chunks)
__device__ float g_z1[16*8*256];       // conv1 out (residual base)
__device__ float g_cm[128];            // per (b,c) GN mean
__device__ float g_cr[128];            // per (b,c) GN rstd
__device__ float g_pd[256*256];        // attn partial denominators [b,h,chunk][row]
__device__ float g_pa0[256*256];       // attn partial numerators ch0
__device__ float g_pa1[256*256];       // attn partial numerators ch1
__device__ float g_apad[16*8*18*18];   // silu(gn2) 16x16, zero-padded border

__device__ __forceinline__ float siluf(float x){
    return __fdividef(x, 1.0f+__expf(-x));
}

__device__ __forceinline__ float redsum256(float v, float* sb){
    #pragma unroll
    for(int o=16;o;o>>=1) v += __shfl_xor_sync(0xffffffffu, v, o);
    if((threadIdx.x&31)==0) sb[threadIdx.x>>5]=v;
    __syncthreads();
    float r = sb[0]+sb[1]+sb[2]+sb[3]+sb[4]+sb[5]+sb[6]+sb[7];
    __syncthreads();
    return r;
}

// ---- K1: 4x4 average pool + exact per-plane stats ----
__global__ void k_pool(const float* __restrict__ x){
    __shared__ float sb[8];
    int plane = blockIdx.x;            // b*320 + c
    int t = threadIdx.x;
    int Y = t>>4, X = t&15;
    const float4* xr = (const float4*)(x + (size_t)plane*4096);
    float s = 0.f;
    #pragma unroll
    for(int r=0;r<4;r++){
        float4 v = xr[(4*Y+r)*16 + X];
        s += v.x+v.y+v.z+v.w;
    }
    float v = s*(1.0f/16.0f);
    g_z[plane*256 + t] = v;
    float P = redsum256(v, sb);
    float Q = redsum256(v*v, sb);
    if(t==0){ g_ps[plane]=P; g_ps2[plane]=Q; }
}

// ---- K2: conv1 (320->8, 3x3 SAME, 16x16), GN1+SiLU fused; 10-ch chunks = groups ----
__global__ void __launch_bounds__(256) k_conv1(const float* __restrict__ g1,
                                               const float* __restrict__ b1,
                                               const float* __restrict__ w1){
    __shared__ float sp[10*324];
    __shared__ __align__(16) float sw[10*72];    // [ci][k][o]
    __shared__ float sms, srs;
    int j = blockIdx.x, b = blockIdx.y;          // chunk j == GN group j
    int t = threadIdx.x;
    if(t==0){
        float s=0.f,s2=0.f;
        #pragma unroll
        for(int i=0;i<10;i++){
            int pl = b*320 + j*10 + i;
            s += g_ps[pl]; s2 += g_ps2[pl];
        }
        float m = s*(1.0f/2560.0f);
        sms=m; srs=rsqrtf(s2*(1.0f/2560.0f)-m*m+EPSV);
    }
    for(int i=t;i<720;i+=256){
        int ci = i/72, r = i-ci*72, k = r>>3, o = r&7;
        sw[i] = w1[o*2880 + (j*10+ci)*9 + k];
    }
    __syncthreads();
    float m = sms, rs = srs;
    for(int i=t;i<3240;i+=256){
        int ci = i/324, p = i-ci*324;
        int r18 = p/18, c18 = p-r18*18;
        float val = 0.f;
        if(r18>=1 && r18<=16 && c18>=1 && c18<=16){
            int c = j*10+ci;
            float v = g_z[((b*320+c)<<8) + (r18-1)*16 + (c18-1)];
            val = siluf((v-m)*rs*g1[c] + b1[c]);
        }
        sp[i]=val;
    }
    __syncthreads();
    int Y = t>>4, X = t&15;
    float acc[8];
    #pragma unroll
    for(int o=0;o<8;o++) acc[o]=0.f;
    #pragma unroll
    for(int ci=0;ci<10;ci++){
        float a[9];
        #pragma unroll
        for(int dy=0;dy<3;dy++)
            #pragma unroll
            for(int dx=0;dx<3;dx++)
                a[dy*3+dx] = sp[ci*324 + (Y+dy)*18 + (X+dx)];
        #pragma unroll
        for(int k=0;k<9;k++){
            float av = a[k];
            float4 wA = *(const float4*)&sw[((ci*9+k)<<3)];
            float4 wB = *(const float4*)&sw[((ci*9+k)<<3)+4];
            acc[0]+=av*wA.x; acc[1]+=av*wA.y; acc[2]+=av*wA.z; acc[3]+=av*wA.w;
            acc[4]+=av*wB.x; acc[5]+=av*wB.y; acc[6]+=av*wB.z; acc[7]+=av*wB.w;
        }
    }
    #pragma unroll
    for(int o=0;o<8;o++)
        g_z1p[(((j*16+b)*8+o)<<8) + t] = acc[o];
}

// ---- K3: merge partials + bias; per-channel GN stats ----
__global__ void k_merge(const float* __restrict__ bc1){
    __shared__ float sb[8];
    int bc = blockIdx.x;               // b*8 + c
    int b = bc>>3, c = bc&7;
    int t = threadIdx.x;
    float s = bc1[c];
    #pragma unroll
    for(int jj=0;jj<32;jj++)
        s += g_z1p[(((jj*16+b)*8+c)<<8) + t];
    g_z1[bc*256 + t] = s;
    float P = redsum256(s, sb);
    float Q = redsum256(s*s, sb);
    if(t==0){
        float m = P*(1.f/256.f);
        g_cm[bc]=m;
        g_cr[bc]=rsqrtf(Q*(1.f/256.f)-m*m+EPSV);
    }
}

// ---- K4: GN-apply + qkv + split-K attention partials; block=(b,h,chunk) ----
// Softmax without max-pass (|logits|<<1); den/a0/a1 additive across key chunks.
__global__ void __launch_bounds__(256) k_attn(const float* __restrict__ ga,
                                              const float* __restrict__ ba,
                                              const float* __restrict__ wq,
                                              const float* __restrict__ bq){
    __shared__ float2 sk[256], sv[256];
    __shared__ float swq[192];
    int blk = blockIdx.x;              // b*16 + h*4 + chunk
    int b = blk>>4, h = (blk>>2)&3, ch = blk&3;
    int t = threadIdx.x;               // row
    if(t<192) swq[t] = wq[t];
    __syncthreads();
    float nv[8];
    #pragma unroll
    for(int c=0;c<8;c++){
        int bc = b*8+c;
        float z = g_z1[bc*256+t];
        nv[c] = (z-g_cm[bc])*g_cr[bc]*ga[c] + ba[c];
    }
    float q0=bq[2*h], q1=bq[2*h+1];
    float k0=bq[8+2*h], k1=bq[9+2*h];
    float v0=bq[16+2*h], v1=bq[17+2*h];
    #pragma unroll
    for(int c=0;c<8;c++){
        q0 += swq[(2*h  )*8+c]*nv[c];
        q1 += swq[(2*h+1)*8+c]*nv[c];
        k0 += swq[(8+2*h)*8+c]*nv[c];
        k1 += swq[(9+2*h)*8+c]*nv[c];
        v0 += swq[(16+2*h)*8+c]*nv[c];
        v1 += swq[(17+2*h)*8+c]*nv[c];
    }
    sk[t] = make_float2(k0,k1);
    sv[t] = make_float2(v0,v1);
    const float scale = 0.7071067811865475f;
    q0*=scale; q1*=scale;
    __syncthreads();
    float den=0.f, a0=0.f, a1=0.f;
    int m0 = ch*64;
    #pragma unroll 8
    for(int m=m0;m<m0+64;m++){          // all lanes same m -> broadcast LDS
        float2 kk = sk[m];
        float e = __expf(q0*kk.x + q1*kk.y);
        float2 vv = sv[m];
        den += e;
        a0 += e*vv.x; a1 += e*vv.y;
    }
    g_pd [blk*256 + t] = den;
    g_pa0[blk*256 + t] = a0;
    g_pa1[blk*256 + t] = a1;
}

// ---- K5: combine attn partials + proj+res + LN + MLP(gelu) + res + GN2 + SiLU ----
__global__ void __launch_bounds__(256) k_mlpapad(
        const float* __restrict__ wp, const float* __restrict__ bp,
        const float* __restrict__ lng, const float* __restrict__ lnb,
        const float* __restrict__ wf1, const float* __restrict__ bf1,
        const float* __restrict__ wf2, const float* __restrict__ bf2,
        const float* __restrict__ g2, const float* __restrict__ b2){
    __shared__ float sred[16*8];
    __shared__ float sredt[16];
    int b = blockIdx.x, t = threadIdx.x;   // t = pixel
    float ao[8];
    #pragma unroll
    for(int h=0;h<4;h++){
        float den=0.f, s0=0.f, s1=0.f;
        #pragma unroll
        for(int ch=0;ch<4;ch++){
            int base = ((b*4+h)*4+ch)*256 + t;
            den += g_pd[base]; s0 += g_pa0[base]; s1 += g_pa1[base];
        }
        float inv = __fdividef(1.0f, den);
        ao[2*h]   = s0*inv;
        ao[2*h+1] = s1*inv;
    }
    float z2[8];
    #pragma unroll
    for(int c=0;c<8;c++){
        float s = bp[c] + g_z1[(b*8+c)*256+t];
        #pragma unroll
        for(int d=0;d<8;d++) s += wp[c*8+d]*ao[d];
        z2[c]=s;
    }
    float mu=0.f;
    #pragma unroll
    for(int c=0;c<8;c++) mu += z2[c];
    mu *= 0.125f;
    float var=0.f;
    #pragma unroll
    for(int c=0;c<8;c++){ float d=z2[c]-mu; var += d*d; }
    float rsl = rsqrtf(var*0.125f + EPSV);
    float ln[8];
    #pragma unroll
    for(int c=0;c<8;c++) ln[c] = (z2[c]-mu)*rsl*lng[c] + lnb[c];
    float hg[16];
    #pragma unroll
    for(int jj=0;jj<16;jj++){
        float s = bf1[jj];
        #pragma unroll
        for(int c=0;c<8;c++) s += wf1[jj*8+c]*ln[c];
        hg[jj] = 0.5f*s*(1.0f + erff(s*0.7071067811865475f));
    }
    float z3[8];
    #pragma unroll
    for(int c=0;c<8;c++){
        float s = z2[c] + bf2[c];
        #pragma unroll
        for(int jj=0;jj<16;jj++) s += wf2[c*16+jj]*hg[jj];
        z3[c]=s;
    }
    // GN2 stats: batched 16-way reduce (8 sums + 8 sumsqs)
    float red[16];
    #pragma unroll
    for(int c=0;c<8;c++){ red[c]=z3[c]; red[8+c]=z3[c]*z3[c]; }
    #pragma unroll
    for(int q=0;q<16;q++)
        #pragma unroll
        for(int o=16;o;o>>=1) red[q] += __shfl_xor_sync(0xffffffffu, red[q], o);
    if((t&31)==0){
        #pragma unroll
        for(int q=0;q<16;q++) sred[q*8 + (t>>5)] = red[q];
    }
    __syncthreads();
    if(t<16){
        float tot=0.f;
        #pragma unroll
        for(int w=0;w<8;w++) tot += sred[t*8+w];
        sredt[t]=tot;
    }
    __syncthreads();
    int Y=t>>4, X=t&15;
    #pragma unroll
    for(int c=0;c<8;c++){
        float m = sredt[c]*(1.f/256.f);
        float rs = rsqrtf(sredt[8+c]*(1.f/256.f)-m*m+EPSV);
        float a = siluf((z3[c]-m)*rs*g2[c] + b2[c]);
        g_apad[(b*8+c)*324 + (Y+1)*18 + (X+1)] = a;
    }
}

// ---- K6: fused upsample+conv2 (8->320) as stride-4 transposed conv ----
__global__ void __launch_bounds__(256) k_conv2(const float* __restrict__ w2,
                                               const float* __restrict__ bc2,
                                               float* __restrict__ out){
    __shared__ __align__(8) float sa[2592];   // a_pad[b]: 8 x 18 x 18
    __shared__ __align__(8) float sw[1152];   // collapsed 6x6 weights for 4 o-channels
    int og = blockIdx.x, b = blockIdx.y;
    int t = threadIdx.x;
    for(int i=t;i<2592;i+=256) sa[i] = g_apad[b*2592+i];
    for(int i=t;i<1152;i+=256){
        int ol=i/288, r=i-ol*288, c=r/36, q=r-c*36, ky=q/6, kx=q-ky*6;
        int o = og*4+ol;
        int dy0 = max(0, 2-ky), dy1 = min(2, 5-ky);
        int dx0 = max(0, 2-kx), dx1 = min(2, 5-kx);
        float s=0.f;
        for(int dy=dy0;dy<=dy1;dy++)
            for(int dx=dx0;dx<=dx1;dx++)
                s += w2[o*72 + c*9 + dy*3 + dx];
        sw[i] = s;
    }
    __syncthreads();
    int ol = t>>6, u = t&63, Yq = u>>2, Xs = u&3;
    int o = og*4+ol;
    float bias = bc2[o];
    float acc[64];
    #pragma unroll
    for(int i=0;i<64;i++) acc[i]=bias;
    const int RYof[6]={3,0,1,2,3,0};
    const int RWof[6]={2,1,1,1,1,0};
    const int XL0[6] ={3,0,1,2,3,0};
    const int SCB[6] ={2,1,1,1,1,0};
    #pragma unroll
    for(int c=0;c<8;c++){
        float aw[3][6];
        #pragma unroll
        for(int r=0;r<3;r++){
            const float2* sar = (const float2*)&sa[(c*18 + Yq + r)*18 + 4*Xs]; // even word off -> 8B aligned
            float2 p0=sar[0], p1=sar[1], p2=sar[2];
            aw[r][0]=p0.x; aw[r][1]=p0.y; aw[r][2]=p1.x;
            aw[r][3]=p1.y; aw[r][4]=p2.x; aw[r][5]=p2.y;
        }
        const float2* wc2 = (const float2*)&sw[(ol*8 + c)*36];   // 36 = even -> aligned
        #pragma unroll
        for(int ky=0;ky<6;ky++){
            int ry = RYof[ky], riw = RWof[ky];
            float2 wA = wc2[ky*3], wB = wc2[ky*3+1], wC = wc2[ky*3+2];
            float wv[6] = {wA.x, wA.y, wB.x, wB.y, wC.x, wC.y};
            #pragma unroll
            for(int kx=0;kx<6;kx++){
                float w = wv[kx];
                int xl0 = XL0[kx], scb = SCB[kx];
                #pragma unroll
                for(int j=0;j<4;j++)
                    acc[ry*16 + xl0 + 4*j] += w * aw[riw][scb + j];
            }
        }
    }
    float4* ob = (float4*)(out + ((size_t)(b*320 + o)*64 + 4*Yq)*64 + 16*Xs);
    #pragma unroll
    for(int ry=0;ry<4;ry++)
        #pragma unroll
        for(int j=0;j<4;j++)
            ob[ry*16 + j] = make_float4(acc[ry*16+j*4], acc[ry*16+j*4+1],
                                        acc[ry*16+j*4+2], acc[ry*16+j*4+3]);
}

extern "C" void kernel_launch(void* const* d_in, const int* in_sizes, int n_in,
                              void* d_out, int out_size) {
    const float* x   = (const float*)d_in[0];
    const float* g1  = (const float*)d_in[1];
    const float* b1  = (const float*)d_in[2];
    const float* w1  = (const float*)d_in[3];
    const float* bc1 = (const float*)d_in[4];
    const float* ga  = (const float*)d_in[5];
    const float* ba  = (const float*)d_in[6];
    const float* wq  = (const float*)d_in[7];
    const float* bq  = (const float*)d_in[8];
    const float* wp  = (const float*)d_in[9];
    const float* bp  = (const float*)d_in[10];
    const float* lng = (const float*)d_in[11];
    const float* lnb = (const float*)d_in[12];
    const float* wf1 = (const float*)d_in[13];
    const float* bf1 = (const float*)d_in[14];
    const float* wf2 = (const float*)d_in[15];
    const float* bf2 = (const float*)d_in[16];
    const float* g2  = (const float*)d_in[17];
    const float* b2  = (const float*)d_in[18];
    const float* w2  = (const float*)d_in[19];
    const float* bc2 = (const float*)d_in[20];
    float* out = (float*)d_out;

    k_pool   <<<5120, 256>>>(x);
    k_conv1  <<<dim3(32,16), 256>>>(g1, b1, w1);
    k_merge  <<<128, 256>>>(bc1);
    k_attn   <<<256, 256>>>(ga, ba, wq, bq);
    k_mlpapad<<<16, 256>>>(wp, bp, lng, lnb, wf1, bf1, wf2, bf2, g2, b2);
    k_conv2  <<<dim3(80,16), 256>>>(w2, bc2, out);
}